// round 1
// baseline (speedup 1.0000x reference)
#include <cuda_runtime.h>
#include <cstdint>

// ---------------- problem constants ----------------
#define Bz   8
#define Np   64      // patches per image
#define Dd   4096    // attention dim
#define Tt   64
#define TD   512
#define WD   512
#define SLOPE 0.01f

// ---------------- scratch (static device globals; no allocation) ------------
__device__ float g_hs [Bz * 65 * Dd];   // patches + style token
__device__ float g_q  [Bz * 65 * Dd];
__device__ float g_k  [Bz * 65 * Dd];
__device__ float g_v  [Bz * 65 * Dd];
__device__ float g_wts[Bz * 65 * 65];
__device__ float g_a  [Bz * 64 * Dd];   // attention output (keys 0..63)
__device__ float g_h  [Bz * 64 * Dd];   // post-projection hidden

// ---------------- patchify: x NCHW -> hs (B,65,D) rows 0..63 ----------------
__global__ void patchify_kernel(const float* __restrict__ x, float* __restrict__ hs)
{
    int idx = blockIdx.x * blockDim.x + threadIdx.x;
    if (idx >= Bz * 64 * Dd) return;
    int d  = idx & 4095;
    int n  = (idx >> 12) & 63;
    int b  = idx >> 18;
    int c  = d & 63;
    int pp = d >> 6;          // pr*8 + pc
    int pr = pp >> 3, pc = pp & 7;
    int ib = n >> 3, jb = n & 7;
    int y  = jb * 8 + pr;
    int xw = ib * 8 + pc;
    hs[((size_t)b * 65 + n) * Dd + d] =
        x[(((size_t)b * 64 + c) * 64 + y) * 64 + xw];
}

// ---------------- style token: hs row 64 = w @ style_w + style_b ------------
__global__ void style_kernel(const float* __restrict__ w, const float* __restrict__ sw,
                             const float* __restrict__ sb, float* __restrict__ hs)
{
    int o = blockIdx.x * blockDim.x + threadIdx.x;   // 0..4095
    int b = blockIdx.y;
    const float* wb = w + (size_t)b * WD;
    float acc = sb[o];
    #pragma unroll 4
    for (int k = 0; k < WD; k++)
        acc += wb[k] * sw[(size_t)k * Dd + o];
    hs[((size_t)b * 65 + 64) * Dd + o] = acc;
}

// ---------------- SGEMM: C[M,N] = A[M,K] @ W[K,N] + bias, optional leaky ----
// BM=BN=64, BK=16, 256 threads, 4x4 per thread.
__global__ __launch_bounds__(256)
void sgemm_kernel(const float* __restrict__ A, const float* __restrict__ W,
                  const float* __restrict__ bias, float* __restrict__ C,
                  int M, int K, int N, int act)
{
    __shared__ float As[16][64];
    __shared__ float Bs[16][64];
    const int bn = blockIdx.x * 64;
    const int bm = blockIdx.y * 64;
    const int tid = threadIdx.x;
    const int tr = tid >> 4;   // 0..15
    const int tc = tid & 15;   // 0..15

    float acc[4][4] = {};

    for (int k0 = 0; k0 < K; k0 += 16) {
        #pragma unroll
        for (int i = 0; i < 4; i++) {
            int idx = tid + i * 256;
            int m = idx >> 4;
            int k = idx & 15;
            int gm = bm + m;
            As[k][m] = (gm < M) ? A[(size_t)gm * K + k0 + k] : 0.f;
        }
        #pragma unroll
        for (int i = 0; i < 4; i++) {
            int idx = tid + i * 256;
            int k = idx >> 6;
            int n = idx & 63;
            Bs[k][n] = W[(size_t)(k0 + k) * N + bn + n];
        }
        __syncthreads();
        #pragma unroll
        for (int k = 0; k < 16; k++) {
            float a0 = As[k][tr * 4 + 0];
            float a1 = As[k][tr * 4 + 1];
            float a2 = As[k][tr * 4 + 2];
            float a3 = As[k][tr * 4 + 3];
            float b0 = Bs[k][tc * 4 + 0];
            float b1 = Bs[k][tc * 4 + 1];
            float b2 = Bs[k][tc * 4 + 2];
            float b3 = Bs[k][tc * 4 + 3];
            acc[0][0] += a0 * b0; acc[0][1] += a0 * b1; acc[0][2] += a0 * b2; acc[0][3] += a0 * b3;
            acc[1][0] += a1 * b0; acc[1][1] += a1 * b1; acc[1][2] += a1 * b2; acc[1][3] += a1 * b3;
            acc[2][0] += a2 * b0; acc[2][1] += a2 * b1; acc[2][2] += a2 * b2; acc[2][3] += a2 * b3;
            acc[3][0] += a3 * b0; acc[3][1] += a3 * b1; acc[3][2] += a3 * b2; acc[3][3] += a3 * b3;
        }
        __syncthreads();
    }

    #pragma unroll
    for (int u = 0; u < 4; u++) {
        int row = bm + tr * 4 + u;
        if (row >= M) continue;
        #pragma unroll
        for (int v = 0; v < 4; v++) {
            int col = bn + tc * 4 + v;
            float val = acc[u][v] + bias[col];
            if (act) val = (val >= 0.f) ? val : SLOPE * val;
            C[(size_t)row * N + col] = val;
        }
    }
}

// ---------------- L2-attention scores + softmax ------------------------------
// score[i,j] = 2*q_i.k_j - |k_j|^2  (|q_i|^2 cancels in softmax over j)
// One block per (query i, batch b). 256 threads = 8 warps.
__global__ __launch_bounds__(256)
void attn_scores_kernel(const float* __restrict__ Q, const float* __restrict__ Km,
                        float* __restrict__ Wts,
                        int Sq, int Sk, int qbs, int kbs)
{
    int b = blockIdx.y;
    int i = blockIdx.x;
    const float* q     = Q  + ((size_t)b * qbs + i) * Dd;
    const float* kbase = Km + (size_t)b * kbs * Dd;

    __shared__ float sc[80];
    int warp = threadIdx.x >> 5;
    int lane = threadIdx.x & 31;

    for (int j = warp; j < Sk; j += 8) {
        const float* krow = kbase + (size_t)j * Dd;
        float dot = 0.f, kn = 0.f;
        for (int d = lane; d < Dd; d += 32) {
            float kv = krow[d];
            dot += q[d] * kv;
            kn  += kv * kv;
        }
        #pragma unroll
        for (int off = 16; off; off >>= 1) {
            dot += __shfl_down_sync(0xffffffff, dot, off);
            kn  += __shfl_down_sync(0xffffffff, kn, off);
        }
        if (lane == 0) sc[j] = 2.f * dot - kn;
    }
    __syncthreads();

    if (threadIdx.x == 0) {
        float mx = -1e30f;
        for (int j = 0; j < Sk; j++) mx = fmaxf(mx, sc[j]);
        float sum = 0.f;
        for (int j = 0; j < Sk; j++) { float e = __expf(sc[j] - mx); sc[j] = e; sum += e; }
        float inv = 1.f / sum;
        float* wrow = Wts + ((size_t)b * Sq + i) * Sk;
        for (int j = 0; j < Sk; j++) wrow[j] = sc[j] * inv;
    }
}

// ---------------- attention output over keys: out[j] = sum_i w[i,j] v[i] ----
// One block per (key j in 0..63, batch b). Output is (B,64,D) contiguous.
__global__ __launch_bounds__(256)
void attn_out_kernel(const float* __restrict__ Wts, const float* __restrict__ V,
                     float* __restrict__ Out, int Sq, int Sk, int vbs)
{
    int b = blockIdx.y;
    int j = blockIdx.x;  // 0..63
    __shared__ float sw[80];
    for (int i = threadIdx.x; i < Sq; i += blockDim.x)
        sw[i] = Wts[((size_t)b * Sq + i) * Sk + j];
    __syncthreads();

    const float* vb = V + (size_t)b * vbs * Dd;
    float* o = Out + ((size_t)b * 64 + j) * Dd;
    for (int d = threadIdx.x; d < Dd; d += 256) {
        float acc = 0.f;
        for (int i = 0; i < Sq; i++)
            acc += sw[i] * vb[(size_t)i * Dd + d];
        o[d] = acc;
    }
}

// ---------------- depatchify: g_h (B,64,D) -> out NCHW (B,64,64,64) ----------
__global__ void depatchify_kernel(const float* __restrict__ h, float* __restrict__ out)
{
    int idx = blockIdx.x * blockDim.x + threadIdx.x;
    if (idx >= Bz * 64 * 64 * 64) return;
    int xw = idx & 63;
    int y  = (idx >> 6) & 63;
    int c  = (idx >> 12) & 63;
    int b  = idx >> 18;
    int jb = y >> 3, pr = y & 7;
    int ib = xw >> 3, pc = xw & 7;
    int n = ib * 8 + jb;
    int d = (pr * 8 + pc) * 64 + c;
    out[idx] = h[((size_t)b * 64 + n) * Dd + d];
}

// ---------------- host launch sequence ---------------------------------------
static void launch_gemm(const float* A, const float* W, const float* bias,
                        float* C, int M, int K, int N, int act)
{
    dim3 grid(N / 64, (M + 63) / 64);
    sgemm_kernel<<<grid, 256>>>(A, W, bias, C, M, K, N, act);
}

extern "C" void kernel_launch(void* const* d_in, const int* in_sizes, int n_in,
                              void* d_out, int out_size)
{
    const float* x        = (const float*)d_in[0];
    const float* w        = (const float*)d_in[1];
    const float* t_local  = (const float*)d_in[2];
    const float* sa_style_w = (const float*)d_in[3];
    const float* sa_style_b = (const float*)d_in[4];
    const float* sa_kk = (const float*)d_in[5];
    const float* sa_kb = (const float*)d_in[6];
    const float* sa_qk = (const float*)d_in[7];
    const float* sa_qb = (const float*)d_in[8];
    const float* sa_vk = (const float*)d_in[9];
    const float* sa_vb = (const float*)d_in[10];
    const float* sa_ok = (const float*)d_in[11];
    const float* sa_ob = (const float*)d_in[12];
    const float* ca_kk = (const float*)d_in[13];
    const float* ca_kb = (const float*)d_in[14];
    const float* ca_qk = (const float*)d_in[15];
    const float* ca_qb = (const float*)d_in[16];
    const float* ca_vk = (const float*)d_in[17];
    const float* ca_vb = (const float*)d_in[18];
    const float* ca_ok = (const float*)d_in[19];
    const float* ca_ob = (const float*)d_in[20];
    float* out = (float*)d_out;

    float *hs, *q, *k, *v, *wts, *a, *h;
    cudaGetSymbolAddress((void**)&hs,  g_hs);
    cudaGetSymbolAddress((void**)&q,   g_q);
    cudaGetSymbolAddress((void**)&k,   g_k);
    cudaGetSymbolAddress((void**)&v,   g_v);
    cudaGetSymbolAddress((void**)&wts, g_wts);
    cudaGetSymbolAddress((void**)&a,   g_a);
    cudaGetSymbolAddress((void**)&h,   g_h);

    // 1. patchify + style token -> hs (B,65,D)
    patchify_kernel<<<(Bz * 64 * Dd + 255) / 256, 256>>>(x, hs);
    style_kernel<<<dim3(Dd / 256, Bz), 256>>>(w, sa_style_w, sa_style_b, hs);

    // 2. SA q/k/v projections: (520,4096) @ (4096,4096)
    launch_gemm(hs, sa_qk, sa_qb, q, Bz * 65, Dd, Dd, 0);
    launch_gemm(hs, sa_kk, sa_kb, k, Bz * 65, Dd, Dd, 0);
    launch_gemm(hs, sa_vk, sa_vb, v, Bz * 65, Dd, Dd, 0);

    // 3. SA L2 attention (Sq=Sk=65, output keys 0..63)
    attn_scores_kernel<<<dim3(65, Bz), 256>>>(q, k, wts, 65, 65, 65, 65);
    attn_out_kernel<<<dim3(64, Bz), 256>>>(wts, v, a, 65, 65, 65);

    // 4. SA output projection + leaky relu -> h
    launch_gemm(a, sa_ok, sa_ob, h, Bz * 64, Dd, Dd, 1);

    // 5. CA projections: k from h (4096->4096), q/v from t_local (512->4096)
    launch_gemm(h,       ca_kk, ca_kb, k, Bz * 64, Dd, Dd, 0);
    launch_gemm(t_local, ca_qk, ca_qb, q, Bz * 64, TD, Dd, 0);
    launch_gemm(t_local, ca_vk, ca_vb, v, Bz * 64, TD, Dd, 0);

    // 6. CA L2 attention (Sq=T=64 queries, Sk=N=64 keys)
    attn_scores_kernel<<<dim3(64, Bz), 256>>>(q, k, wts, 64, 64, 64, 64);
    attn_out_kernel<<<dim3(64, Bz), 256>>>(wts, v, a, 64, 64, 64);

    // 7. CA output projection + leaky relu -> h
    launch_gemm(a, ca_ok, ca_ob, h, Bz * 64, Dd, Dd, 1);

    // 8. depatchify -> NCHW output
    depatchify_kernel<<<(Bz * 64 * 64 * 64 + 255) / 256, 256>>>(h, out);
}

// round 3
// speedup vs baseline: 3.3219x; 3.3219x over previous
#include <cuda_runtime.h>
#include <cstdint>

// ---------------- problem constants ----------------
#define Bz   8
#define Dd   4096
#define TD   512
#define WD   512
#define SLOPE 0.01f

// ---------------- scratch (static device globals) ----------------
__device__ float g_hs [Bz * 65 * Dd];
__device__ float g_q  [Bz * 65 * Dd];
__device__ float g_k  [Bz * 65 * Dd];
__device__ float g_v  [Bz * 65 * Dd];
__device__ float g_wts[Bz * 65 * 65];
__device__ float g_a  [Bz * 64 * Dd];
__device__ float g_h  [Bz * 64 * Dd];

// ---------------- tf32 mma.sync GEMM ----------------
// C[M,4096] = A[M,K] @ W[K,4096] + bias (+leaky).  W row-major (K,N), N contig.
// CTA 128x128, BK=32, 256 threads, warp grid 2(M) x 4(N), warp tile 64x32.
// smem: A [128][36] floats, B [32][136] floats, double buffered.

#define ASTRIDE 36
#define BSTRIDE 136
#define A_FLOATS (128 * ASTRIDE)          // 4608
#define B_FLOATS (32 * BSTRIDE)           // 4352
#define STAGE_FLOATS (A_FLOATS + B_FLOATS)
#define GEMM_SMEM (2 * STAGE_FLOATS * 4)  // 71680 bytes

__device__ __forceinline__ uint32_t smem_u32(const void* p) {
    uint32_t a;
    asm("{ .reg .u64 t; cvta.to.shared.u64 t, %1; cvt.u32.u64 %0, t; }" : "=r"(a) : "l"(p));
    return a;
}
__device__ __forceinline__ void cp16(uint32_t dst, const void* src, int pred16) {
    asm volatile("cp.async.ca.shared.global [%0], [%1], 16, %2;"
                 :: "r"(dst), "l"(src), "r"(pred16) : "memory");
}
__device__ __forceinline__ uint32_t f2tf32(float x) {
    uint32_t u;
    asm("cvt.rna.tf32.f32 %0, %1;" : "=r"(u) : "f"(x));
    return u;
}

__global__ __launch_bounds__(256, 1)
void mma_gemm(const float* __restrict__ A, const float* __restrict__ W,
              const float* __restrict__ bias, float* __restrict__ C,
              int M, int K, int act)
{
    extern __shared__ __align__(16) float sm[];
    const uint32_t smaddr = smem_u32(sm);
    const int tid  = threadIdx.x;
    const int wid  = tid >> 5;
    const int lane = tid & 31;
    const int bn = blockIdx.x << 7;
    const int bm = blockIdx.y << 7;
    const int wm = (wid >> 2) << 6;   // 0 or 64
    const int wn = (wid & 3) << 5;    // 0,32,64,96
    const int r  = lane >> 2;         // 0..7
    const int c  = lane & 3;          // 0..3

    float acc[4][4][4];
    #pragma unroll
    for (int i = 0; i < 4; i++)
        #pragma unroll
        for (int j = 0; j < 4; j++)
            #pragma unroll
            for (int t = 0; t < 4; t++) acc[i][j][t] = 0.f;

    const int nkb = K >> 5;

    // stage loader: copy k-block kb into buffer buf
    auto load_stage = [&](int kb, int buf) {
        const int kcol = kb << 5;
        uint32_t abase = smaddr + (uint32_t)buf * STAGE_FLOATS * 4;
        uint32_t bbase = abase + A_FLOATS * 4;
        // A: 128 rows x 8 float4
        #pragma unroll
        for (int i = 0; i < 4; i++) {
            int idx = tid + i * 256;
            int row = idx >> 3;
            int f4  = idx & 7;
            int gm  = bm + row;
            int ok  = (gm < M) ? 16 : 0;
            if (gm >= M) gm = M - 1;
            cp16(abase + (uint32_t)(row * ASTRIDE + f4 * 4) * 4,
                 A + (size_t)gm * K + kcol + f4 * 4, ok);
        }
        // B: 32 rows x 32 float4
        #pragma unroll
        for (int i = 0; i < 4; i++) {
            int idx = tid + i * 256;
            int row = idx >> 5;
            int f4  = idx & 31;
            cp16(bbase + (uint32_t)(row * BSTRIDE + f4 * 4) * 4,
                 W + (size_t)(kcol + row) * 4096 + bn + f4 * 4, 16);
        }
        asm volatile("cp.async.commit_group;" ::: "memory");
    };

    load_stage(0, 0);

    for (int kb = 0; kb < nkb; kb++) {
        if (kb + 1 < nkb) load_stage(kb + 1, (kb + 1) & 1);
        if (kb + 1 < nkb)
            asm volatile("cp.async.wait_group 1;" ::: "memory");
        else
            asm volatile("cp.async.wait_group 0;" ::: "memory");
        __syncthreads();

        const float* as = sm + (kb & 1) * STAGE_FLOATS;
        const float* bs = as + A_FLOATS;

        #pragma unroll
        for (int ks = 0; ks < 4; ks++) {
            const int k0 = ks << 3;
            uint32_t af[4][4];
            #pragma unroll
            for (int mt = 0; mt < 4; mt++) {
                int m = wm + mt * 16 + r;
                af[mt][0] = f2tf32(as[ m      * ASTRIDE + k0 + c    ]);
                af[mt][1] = f2tf32(as[(m + 8) * ASTRIDE + k0 + c    ]);
                af[mt][2] = f2tf32(as[ m      * ASTRIDE + k0 + c + 4]);
                af[mt][3] = f2tf32(as[(m + 8) * ASTRIDE + k0 + c + 4]);
            }
            uint32_t bf[4][2];
            #pragma unroll
            for (int nt = 0; nt < 4; nt++) {
                int n = wn + nt * 8 + r;
                bf[nt][0] = f2tf32(bs[(k0 + c)     * BSTRIDE + n]);
                bf[nt][1] = f2tf32(bs[(k0 + 4 + c) * BSTRIDE + n]);
            }
            #pragma unroll
            for (int mt = 0; mt < 4; mt++)
                #pragma unroll
                for (int nt = 0; nt < 4; nt++) {
                    asm volatile(
                        "mma.sync.aligned.m16n8k8.row.col.f32.tf32.tf32.f32 "
                        "{%0,%1,%2,%3}, {%4,%5,%6,%7}, {%8,%9}, {%0,%1,%2,%3};"
                        : "+f"(acc[mt][nt][0]), "+f"(acc[mt][nt][1]),
                          "+f"(acc[mt][nt][2]), "+f"(acc[mt][nt][3])
                        : "r"(af[mt][0]), "r"(af[mt][1]), "r"(af[mt][2]), "r"(af[mt][3]),
                          "r"(bf[nt][0]), "r"(bf[nt][1]));
                }
        }
        __syncthreads();
    }

    // epilogue
    #pragma unroll
    for (int mt = 0; mt < 4; mt++) {
        int row0 = bm + wm + mt * 16 + r;
        int row1 = row0 + 8;
        #pragma unroll
        for (int nt = 0; nt < 4; nt++) {
            int col = bn + wn + nt * 8 + c * 2;
            float b0 = bias[col], b1 = bias[col + 1];
            if (row0 < M) {
                float v0 = acc[mt][nt][0] + b0;
                float v1 = acc[mt][nt][1] + b1;
                if (act) { v0 = v0 >= 0.f ? v0 : SLOPE * v0; v1 = v1 >= 0.f ? v1 : SLOPE * v1; }
                *(float2*)(C + (size_t)row0 * 4096 + col) = make_float2(v0, v1);
            }
            if (row1 < M) {
                float v2 = acc[mt][nt][2] + b0;
                float v3 = acc[mt][nt][3] + b1;
                if (act) { v2 = v2 >= 0.f ? v2 : SLOPE * v2; v3 = v3 >= 0.f ? v3 : SLOPE * v3; }
                *(float2*)(C + (size_t)row1 * 4096 + col) = make_float2(v2, v3);
            }
        }
    }
}

// ---------------- patchify ----------------
__global__ void patchify_kernel(const float* __restrict__ x, float* __restrict__ hs)
{
    int idx = blockIdx.x * blockDim.x + threadIdx.x;
    if (idx >= Bz * 64 * Dd) return;
    int d  = idx & 4095;
    int n  = (idx >> 12) & 63;
    int b  = idx >> 18;
    int cc = d & 63;
    int pp = d >> 6;
    int pr = pp >> 3, pc = pp & 7;
    int ib = n >> 3, jb = n & 7;
    int y  = jb * 8 + pr;
    int xw = ib * 8 + pc;
    hs[((size_t)b * 65 + n) * Dd + d] =
        x[(((size_t)b * 64 + cc) * 64 + y) * 64 + xw];
}

// ---------------- style token ----------------
__global__ void style_kernel(const float* __restrict__ w, const float* __restrict__ sw,
                             const float* __restrict__ sb, float* __restrict__ hs)
{
    int o = blockIdx.x * blockDim.x + threadIdx.x;
    int b = blockIdx.y;
    const float* wb = w + (size_t)b * WD;
    float acc = sb[o];
    #pragma unroll 4
    for (int k = 0; k < WD; k++)
        acc += wb[k] * sw[(size_t)k * Dd + o];
    hs[((size_t)b * 65 + 64) * Dd + o] = acc;
}

// ---------------- L2-attention scores + softmax ----------------
__global__ __launch_bounds__(256)
void attn_scores_kernel(const float* __restrict__ Q, const float* __restrict__ Km,
                        float* __restrict__ Wts, int Sq, int Sk, int qbs, int kbs)
{
    int b = blockIdx.y;
    int i = blockIdx.x;
    const float* q     = Q  + ((size_t)b * qbs + i) * Dd;
    const float* kbase = Km + (size_t)b * kbs * Dd;

    __shared__ float sc[80];
    int warp = threadIdx.x >> 5;
    int lane = threadIdx.x & 31;

    for (int j = warp; j < Sk; j += 8) {
        const float* krow = kbase + (size_t)j * Dd;
        float dot = 0.f, kn = 0.f;
        for (int d = lane; d < Dd; d += 32) {
            float kv = krow[d];
            dot += q[d] * kv;
            kn  += kv * kv;
        }
        #pragma unroll
        for (int off = 16; off; off >>= 1) {
            dot += __shfl_down_sync(0xffffffff, dot, off);
            kn  += __shfl_down_sync(0xffffffff, kn, off);
        }
        if (lane == 0) sc[j] = 2.f * dot - kn;
    }
    __syncthreads();

    if (threadIdx.x == 0) {
        float mx = -1e30f;
        for (int j = 0; j < Sk; j++) mx = fmaxf(mx, sc[j]);
        float sum = 0.f;
        for (int j = 0; j < Sk; j++) { float e = __expf(sc[j] - mx); sc[j] = e; sum += e; }
        float inv = 1.f / sum;
        float* wrow = Wts + ((size_t)b * Sq + i) * Sk;
        for (int j = 0; j < Sk; j++) wrow[j] = sc[j] * inv;
    }
}

// ---------------- attention output over keys ----------------
__global__ __launch_bounds__(256)
void attn_out_kernel(const float* __restrict__ Wts, const float* __restrict__ V,
                     float* __restrict__ Out, int Sq, int Sk, int vbs)
{
    int b = blockIdx.y;
    int j = blockIdx.x;
    __shared__ float sw[80];
    for (int i = threadIdx.x; i < Sq; i += blockDim.x)
        sw[i] = Wts[((size_t)b * Sq + i) * Sk + j];
    __syncthreads();

    const float* vb = V + (size_t)b * vbs * Dd;
    float* o = Out + ((size_t)b * 64 + j) * Dd;
    for (int d = threadIdx.x; d < Dd; d += 256) {
        float acc = 0.f;
        for (int i = 0; i < Sq; i++)
            acc += sw[i] * vb[(size_t)i * Dd + d];
        o[d] = acc;
    }
}

// ---------------- depatchify ----------------
__global__ void depatchify_kernel(const float* __restrict__ h, float* __restrict__ out)
{
    int idx = blockIdx.x * blockDim.x + threadIdx.x;
    if (idx >= Bz * 64 * 64 * 64) return;
    int xw = idx & 63;
    int y  = (idx >> 6) & 63;
    int cc = (idx >> 12) & 63;
    int b  = idx >> 18;
    int jb = y >> 3, pr = y & 7;
    int ib = xw >> 3, pc = xw & 7;
    int n = ib * 8 + jb;
    int d = (pr * 8 + pc) * 64 + cc;
    out[idx] = h[((size_t)b * 64 + n) * Dd + d];
}

// ---------------- host sequence ----------------
static void run_gemm(const float* A, const float* W, const float* bias,
                     float* C, int M, int K, int act)
{
    dim3 grid(32, (M + 127) / 128);
    mma_gemm<<<grid, 256, GEMM_SMEM>>>(A, W, bias, C, M, K, act);
}

extern "C" void kernel_launch(void* const* d_in, const int* in_sizes, int n_in,
                              void* d_out, int out_size)
{
    const float* x          = (const float*)d_in[0];
    const float* w          = (const float*)d_in[1];
    const float* t_local    = (const float*)d_in[2];
    const float* sa_style_w = (const float*)d_in[3];
    const float* sa_style_b = (const float*)d_in[4];
    const float* sa_kk = (const float*)d_in[5];
    const float* sa_kb = (const float*)d_in[6];
    const float* sa_qk = (const float*)d_in[7];
    const float* sa_qb = (const float*)d_in[8];
    const float* sa_vk = (const float*)d_in[9];
    const float* sa_vb = (const float*)d_in[10];
    const float* sa_ok = (const float*)d_in[11];
    const float* sa_ob = (const float*)d_in[12];
    const float* ca_kk = (const float*)d_in[13];
    const float* ca_kb = (const float*)d_in[14];
    const float* ca_qk = (const float*)d_in[15];
    const float* ca_qb = (const float*)d_in[16];
    const float* ca_vk = (const float*)d_in[17];
    const float* ca_vb = (const float*)d_in[18];
    const float* ca_ok = (const float*)d_in[19];
    const float* ca_ob = (const float*)d_in[20];
    float* out = (float*)d_out;

    float *hs, *q, *k, *v, *wts, *a, *h;
    cudaGetSymbolAddress((void**)&hs,  g_hs);
    cudaGetSymbolAddress((void**)&q,   g_q);
    cudaGetSymbolAddress((void**)&k,   g_k);
    cudaGetSymbolAddress((void**)&v,   g_v);
    cudaGetSymbolAddress((void**)&wts, g_wts);
    cudaGetSymbolAddress((void**)&a,   g_a);
    cudaGetSymbolAddress((void**)&h,   g_h);

    cudaFuncSetAttribute(mma_gemm, cudaFuncAttributeMaxDynamicSharedMemorySize, GEMM_SMEM);

    // 1. patchify + style token -> hs (B,65,D)
    patchify_kernel<<<(Bz * 64 * Dd + 255) / 256, 256>>>(x, hs);
    style_kernel<<<dim3(Dd / 256, Bz), 256>>>(w, sa_style_w, sa_style_b, hs);

    // 2. SA q/k/v projections (M=520, K=4096)
    run_gemm(hs, sa_qk, sa_qb, q, Bz * 65, Dd, 0);
    run_gemm(hs, sa_kk, sa_kb, k, Bz * 65, Dd, 0);
    run_gemm(hs, sa_vk, sa_vb, v, Bz * 65, Dd, 0);

    // 3. SA L2 attention
    attn_scores_kernel<<<dim3(65, Bz), 256>>>(q, k, wts, 65, 65, 65, 65);
    attn_out_kernel<<<dim3(64, Bz), 256>>>(wts, v, a, 65, 65, 65);

    // 4. SA output projection + leaky relu
    run_gemm(a, sa_ok, sa_ob, h, Bz * 64, Dd, 1);

    // 5. CA projections
    run_gemm(h,       ca_kk, ca_kb, k, Bz * 64, Dd, 0);
    run_gemm(t_local, ca_qk, ca_qb, q, Bz * 64, TD, 0);
    run_gemm(t_local, ca_vk, ca_vb, v, Bz * 64, TD, 0);

    // 6. CA L2 attention
    attn_scores_kernel<<<dim3(64, Bz), 256>>>(q, k, wts, 64, 64, 64, 64);
    attn_out_kernel<<<dim3(64, Bz), 256>>>(wts, v, a, 64, 64, 64);

    // 7. CA output projection + leaky relu
    run_gemm(a, ca_ok, ca_ob, h, Bz * 64, Dd, 1);

    // 8. depatchify
    depatchify_kernel<<<(Bz * 64 * 64 * 64 + 255) / 256, 256>>>(h, out);
}

// round 4
// speedup vs baseline: 3.5450x; 1.0671x over previous
#include <cuda_runtime.h>
#include <cstdint>

// ---------------- problem constants ----------------
#define Bz   8
#define Dd   4096
#define TD   512
#define WD   512
#define SLOPE 0.01f

// ---------------- scratch (static device globals) ----------------
__device__ float g_hs [Bz * 65 * Dd];
__device__ float g_q  [Bz * 65 * Dd];
__device__ float g_k  [Bz * 65 * Dd];
__device__ float g_v  [Bz * 65 * Dd];
__device__ float g_wts[Bz * 65 * 65];
__device__ float g_a  [Bz * 64 * Dd];
__device__ float g_h  [Bz * 64 * Dd];

// ---------------- tf32 mma.sync GEMM (512 threads, fused z-batch) ----------
// C[z][M,4096] = A[M,K] @ W[z][K,4096] + bias[z] (+leaky)
// CTA 128x128, BK=32, warp grid 4(m) x 4(n), warp tile 32x32, 3-stage cp.async.

#define ASTRIDE 36
#define BSTRIDE 136
#define A_FLOATS (128 * ASTRIDE)          // 4608
#define B_FLOATS (32 * BSTRIDE)           // 4352
#define STAGE_FLOATS (A_FLOATS + B_FLOATS)
#define GEMM_SMEM (3 * STAGE_FLOATS * 4)  // 107520 bytes

__device__ __forceinline__ uint32_t smem_u32(const void* p) {
    uint32_t a;
    asm("{ .reg .u64 t; cvta.to.shared.u64 t, %1; cvt.u32.u64 %0, t; }" : "=r"(a) : "l"(p));
    return a;
}
__device__ __forceinline__ void cp16(uint32_t dst, const void* src, int pred16) {
    asm volatile("cp.async.ca.shared.global [%0], [%1], 16, %2;"
                 :: "r"(dst), "l"(src), "r"(pred16) : "memory");
}
__device__ __forceinline__ uint32_t f2tf32(float x) {
    uint32_t u;
    asm("cvt.rna.tf32.f32 %0, %1;" : "=r"(u) : "f"(x));
    return u;
}

__global__ __launch_bounds__(512, 1)
void mma_gemm(const float* __restrict__ A,
              const float* __restrict__ W0, const float* __restrict__ W1,
              const float* __restrict__ W2,
              const float* __restrict__ b0, const float* __restrict__ b1,
              const float* __restrict__ b2,
              float* __restrict__ C0, float* __restrict__ C1, float* __restrict__ C2,
              int M, int K, int act)
{
    const float* W    = (blockIdx.z == 0) ? W0 : (blockIdx.z == 1) ? W1 : W2;
    const float* bias = (blockIdx.z == 0) ? b0 : (blockIdx.z == 1) ? b1 : b2;
    float*       C    = (blockIdx.z == 0) ? C0 : (blockIdx.z == 1) ? C1 : C2;

    extern __shared__ __align__(16) float sm[];
    const uint32_t smaddr = smem_u32(sm);
    const int tid  = threadIdx.x;
    const int wid  = tid >> 5;
    const int lane = tid & 31;
    const int bn = blockIdx.x << 7;
    const int bm = blockIdx.y << 7;
    const int wm = (wid >> 2) << 5;   // 0,32,64,96
    const int wn = (wid & 3) << 5;    // 0,32,64,96
    const int r  = lane >> 2;         // 0..7
    const int c  = lane & 3;          // 0..3

    float acc[2][4][4];
    #pragma unroll
    for (int i = 0; i < 2; i++)
        #pragma unroll
        for (int j = 0; j < 4; j++)
            #pragma unroll
            for (int t = 0; t < 4; t++) acc[i][j][t] = 0.f;

    const int nkb = K >> 5;

    // stage loader: 512 threads, A: 1024 float4, B: 1024 float4 -> 2+2 each
    auto load_stage = [&](int kb, int buf) {
        const int kcol = kb << 5;
        uint32_t abase = smaddr + (uint32_t)buf * STAGE_FLOATS * 4;
        uint32_t bbase = abase + A_FLOATS * 4;
        #pragma unroll
        for (int i = 0; i < 2; i++) {
            int idx = tid + i * 512;
            int row = idx >> 3;
            int f4  = idx & 7;
            int gm  = bm + row;
            int ok  = (gm < M) ? 16 : 0;
            if (gm >= M) gm = M - 1;
            cp16(abase + (uint32_t)(row * ASTRIDE + f4 * 4) * 4,
                 A + (size_t)gm * K + kcol + f4 * 4, ok);
        }
        #pragma unroll
        for (int i = 0; i < 2; i++) {
            int idx = tid + i * 512;
            int row = idx >> 5;
            int f4  = idx & 31;
            cp16(bbase + (uint32_t)(row * BSTRIDE + f4 * 4) * 4,
                 W + (size_t)(kcol + row) * 4096 + bn + f4 * 4, 16);
        }
        asm volatile("cp.async.commit_group;" ::: "memory");
    };

    load_stage(0, 0);
    if (nkb > 1) load_stage(1, 1);

    for (int kb = 0; kb < nkb; kb++) {
        // prefetch kb+2 into buffer (kb+2)%3 (freed by compute(kb-1) sync)
        if (kb + 2 < nkb) load_stage(kb + 2, (kb + 2) % 3);
        // wait until stage kb has landed
        if (kb + 2 < nkb)      asm volatile("cp.async.wait_group 2;" ::: "memory");
        else if (kb + 1 < nkb) asm volatile("cp.async.wait_group 1;" ::: "memory");
        else                   asm volatile("cp.async.wait_group 0;" ::: "memory");
        __syncthreads();

        const float* as = sm + (kb % 3) * STAGE_FLOATS;
        const float* bs = as + A_FLOATS;

        #pragma unroll
        for (int ks = 0; ks < 4; ks++) {
            const int k0 = ks << 3;
            uint32_t af[2][4];
            #pragma unroll
            for (int mt = 0; mt < 2; mt++) {
                int m = wm + mt * 16 + r;
                af[mt][0] = f2tf32(as[ m      * ASTRIDE + k0 + c    ]);
                af[mt][1] = f2tf32(as[(m + 8) * ASTRIDE + k0 + c    ]);
                af[mt][2] = f2tf32(as[ m      * ASTRIDE + k0 + c + 4]);
                af[mt][3] = f2tf32(as[(m + 8) * ASTRIDE + k0 + c + 4]);
            }
            uint32_t bf[4][2];
            #pragma unroll
            for (int nt = 0; nt < 4; nt++) {
                int n = wn + nt * 8 + r;
                bf[nt][0] = f2tf32(bs[(k0 + c)     * BSTRIDE + n]);
                bf[nt][1] = f2tf32(bs[(k0 + 4 + c) * BSTRIDE + n]);
            }
            #pragma unroll
            for (int mt = 0; mt < 2; mt++)
                #pragma unroll
                for (int nt = 0; nt < 4; nt++) {
                    asm volatile(
                        "mma.sync.aligned.m16n8k8.row.col.f32.tf32.tf32.f32 "
                        "{%0,%1,%2,%3}, {%4,%5,%6,%7}, {%8,%9}, {%0,%1,%2,%3};"
                        : "+f"(acc[mt][nt][0]), "+f"(acc[mt][nt][1]),
                          "+f"(acc[mt][nt][2]), "+f"(acc[mt][nt][3])
                        : "r"(af[mt][0]), "r"(af[mt][1]), "r"(af[mt][2]), "r"(af[mt][3]),
                          "r"(bf[nt][0]), "r"(bf[nt][1]));
                }
        }
        __syncthreads();
    }

    // epilogue: bias + optional leaky relu
    #pragma unroll
    for (int mt = 0; mt < 2; mt++) {
        int row0 = bm + wm + mt * 16 + r;
        int row1 = row0 + 8;
        #pragma unroll
        for (int nt = 0; nt < 4; nt++) {
            int col = bn + wn + nt * 8 + c * 2;
            float bb0 = bias[col], bb1 = bias[col + 1];
            if (row0 < M) {
                float v0 = acc[mt][nt][0] + bb0;
                float v1 = acc[mt][nt][1] + bb1;
                if (act) { v0 = v0 >= 0.f ? v0 : SLOPE * v0; v1 = v1 >= 0.f ? v1 : SLOPE * v1; }
                *(float2*)(C + (size_t)row0 * 4096 + col) = make_float2(v0, v1);
            }
            if (row1 < M) {
                float v2 = acc[mt][nt][2] + bb0;
                float v3 = acc[mt][nt][3] + bb1;
                if (act) { v2 = v2 >= 0.f ? v2 : SLOPE * v2; v3 = v3 >= 0.f ? v3 : SLOPE * v3; }
                *(float2*)(C + (size_t)row1 * 4096 + col) = make_float2(v2, v3);
            }
        }
    }
}

// ---------------- patchify ----------------
__global__ void patchify_kernel(const float* __restrict__ x, float* __restrict__ hs)
{
    int idx = blockIdx.x * blockDim.x + threadIdx.x;
    if (idx >= Bz * 64 * Dd) return;
    int d  = idx & 4095;
    int n  = (idx >> 12) & 63;
    int b  = idx >> 18;
    int cc = d & 63;
    int pp = d >> 6;
    int pr = pp >> 3, pc = pp & 7;
    int ib = n >> 3, jb = n & 7;
    int y  = jb * 8 + pr;
    int xw = ib * 8 + pc;
    hs[((size_t)b * 65 + n) * Dd + d] =
        x[(((size_t)b * 64 + cc) * 64 + y) * 64 + xw];
}

// ---------------- style token ----------------
__global__ void style_kernel(const float* __restrict__ w, const float* __restrict__ sw,
                             const float* __restrict__ sb, float* __restrict__ hs)
{
    int o = blockIdx.x * blockDim.x + threadIdx.x;
    int b = blockIdx.y;
    const float* wb = w + (size_t)b * WD;
    float acc = sb[o];
    #pragma unroll 4
    for (int k = 0; k < WD; k++)
        acc += wb[k] * sw[(size_t)k * Dd + o];
    hs[((size_t)b * 65 + 64) * Dd + o] = acc;
}

// ---------------- L2-attention scores + softmax ----------------
__global__ __launch_bounds__(256)
void attn_scores_kernel(const float* __restrict__ Q, const float* __restrict__ Km,
                        float* __restrict__ Wts, int Sq, int Sk, int qbs, int kbs)
{
    int b = blockIdx.y;
    int i = blockIdx.x;
    const float* q     = Q  + ((size_t)b * qbs + i) * Dd;
    const float* kbase = Km + (size_t)b * kbs * Dd;

    __shared__ float sc[80];
    int warp = threadIdx.x >> 5;
    int lane = threadIdx.x & 31;

    for (int j = warp; j < Sk; j += 8) {
        const float* krow = kbase + (size_t)j * Dd;
        float dot = 0.f, kn = 0.f;
        for (int d = lane; d < Dd; d += 32) {
            float kv = krow[d];
            dot += q[d] * kv;
            kn  += kv * kv;
        }
        #pragma unroll
        for (int off = 16; off; off >>= 1) {
            dot += __shfl_down_sync(0xffffffff, dot, off);
            kn  += __shfl_down_sync(0xffffffff, kn, off);
        }
        if (lane == 0) sc[j] = 2.f * dot - kn;
    }
    __syncthreads();

    if (threadIdx.x == 0) {
        float mx = -1e30f;
        for (int j = 0; j < Sk; j++) mx = fmaxf(mx, sc[j]);
        float sum = 0.f;
        for (int j = 0; j < Sk; j++) { float e = __expf(sc[j] - mx); sc[j] = e; sum += e; }
        float inv = 1.f / sum;
        float* wrow = Wts + ((size_t)b * Sq + i) * Sk;
        for (int j = 0; j < Sk; j++) wrow[j] = sc[j] * inv;
    }
}

// ---------------- attention output over keys ----------------
__global__ __launch_bounds__(256)
void attn_out_kernel(const float* __restrict__ Wts, const float* __restrict__ V,
                     float* __restrict__ Out, int Sq, int Sk, int vbs)
{
    int b = blockIdx.y;
    int j = blockIdx.x;
    __shared__ float sw[80];
    for (int i = threadIdx.x; i < Sq; i += blockDim.x)
        sw[i] = Wts[((size_t)b * Sq + i) * Sk + j];
    __syncthreads();

    const float* vb = V + (size_t)b * vbs * Dd;
    float* o = Out + ((size_t)b * 64 + j) * Dd;
    for (int d = threadIdx.x; d < Dd; d += 256) {
        float acc = 0.f;
        for (int i = 0; i < Sq; i++)
            acc += sw[i] * vb[(size_t)i * Dd + d];
        o[d] = acc;
    }
}

// ---------------- depatchify ----------------
__global__ void depatchify_kernel(const float* __restrict__ h, float* __restrict__ out)
{
    int idx = blockIdx.x * blockDim.x + threadIdx.x;
    if (idx >= Bz * 64 * 64 * 64) return;
    int xw = idx & 63;
    int y  = (idx >> 6) & 63;
    int cc = (idx >> 12) & 63;
    int b  = idx >> 18;
    int jb = y >> 3, pr = y & 7;
    int ib = xw >> 3, pc = xw & 7;
    int n = ib * 8 + jb;
    int d = (pr * 8 + pc) * 64 + cc;
    out[idx] = h[((size_t)b * 64 + n) * Dd + d];
}

// ---------------- host sequence ----------------
static void run_gemm3(const float* A,
                      const float* W0, const float* W1, const float* W2,
                      const float* b0, const float* b1, const float* b2,
                      float* C0, float* C1, float* C2,
                      int M, int K, int nz, int act)
{
    dim3 grid(32, (M + 127) / 128, nz);
    mma_gemm<<<grid, 512, GEMM_SMEM>>>(A, W0, W1, W2, b0, b1, b2,
                                       C0, C1, C2, M, K, act);
}

extern "C" void kernel_launch(void* const* d_in, const int* in_sizes, int n_in,
                              void* d_out, int out_size)
{
    const float* x          = (const float*)d_in[0];
    const float* w          = (const float*)d_in[1];
    const float* t_local    = (const float*)d_in[2];
    const float* sa_style_w = (const float*)d_in[3];
    const float* sa_style_b = (const float*)d_in[4];
    const float* sa_kk = (const float*)d_in[5];
    const float* sa_kb = (const float*)d_in[6];
    const float* sa_qk = (const float*)d_in[7];
    const float* sa_qb = (const float*)d_in[8];
    const float* sa_vk = (const float*)d_in[9];
    const float* sa_vb = (const float*)d_in[10];
    const float* sa_ok = (const float*)d_in[11];
    const float* sa_ob = (const float*)d_in[12];
    const float* ca_kk = (const float*)d_in[13];
    const float* ca_kb = (const float*)d_in[14];
    const float* ca_qk = (const float*)d_in[15];
    const float* ca_qb = (const float*)d_in[16];
    const float* ca_vk = (const float*)d_in[17];
    const float* ca_vb = (const float*)d_in[18];
    const float* ca_ok = (const float*)d_in[19];
    const float* ca_ob = (const float*)d_in[20];
    float* out = (float*)d_out;

    float *hs, *q, *k, *v, *wts, *a, *h;
    cudaGetSymbolAddress((void**)&hs,  g_hs);
    cudaGetSymbolAddress((void**)&q,   g_q);
    cudaGetSymbolAddress((void**)&k,   g_k);
    cudaGetSymbolAddress((void**)&v,   g_v);
    cudaGetSymbolAddress((void**)&wts, g_wts);
    cudaGetSymbolAddress((void**)&a,   g_a);
    cudaGetSymbolAddress((void**)&h,   g_h);

    cudaFuncSetAttribute(mma_gemm, cudaFuncAttributeMaxDynamicSharedMemorySize, GEMM_SMEM);

    // 1. patchify + style token -> hs (B,65,D)
    patchify_kernel<<<(Bz * 64 * Dd + 255) / 256, 256>>>(x, hs);
    style_kernel<<<dim3(Dd / 256, Bz), 256>>>(w, sa_style_w, sa_style_b, hs);

    // 2. SA q/k/v projections, fused (M=520, K=4096, z=3)
    run_gemm3(hs, sa_qk, sa_kk, sa_vk, sa_qb, sa_kb, sa_vb,
              q, k, v, Bz * 65, Dd, 3, 0);

    // 3. SA L2 attention
    attn_scores_kernel<<<dim3(65, Bz), 256>>>(q, k, wts, 65, 65, 65, 65);
    attn_out_kernel<<<dim3(64, Bz), 256>>>(wts, v, a, 65, 65, 65);

    // 4. SA output projection + leaky relu
    run_gemm3(a, sa_ok, sa_ok, sa_ok, sa_ob, sa_ob, sa_ob,
              h, h, h, Bz * 64, Dd, 1, 1);

    // 5. CA projections: k from h; q/v from t_local fused (z=2)
    run_gemm3(h, ca_kk, ca_kk, ca_kk, ca_kb, ca_kb, ca_kb,
              k, k, k, Bz * 64, Dd, 1, 0);
    run_gemm3(t_local, ca_qk, ca_vk, ca_vk, ca_qb, ca_vb, ca_vb,
              q, v, v, Bz * 64, TD, 2, 0);

    // 6. CA L2 attention
    attn_scores_kernel<<<dim3(64, Bz), 256>>>(q, k, wts, 64, 64, 64, 64);
    attn_out_kernel<<<dim3(64, Bz), 256>>>(wts, v, a, 64, 64, 64);

    // 7. CA output projection + leaky relu
    run_gemm3(a, ca_ok, ca_ok, ca_ok, ca_ob, ca_ob, ca_ob,
              h, h, h, Bz * 64, Dd, 1, 1);

    // 8. depatchify
    depatchify_kernel<<<(Bz * 64 * 64 * 64 + 255) / 256, 256>>>(h, out);
}

// round 5
// speedup vs baseline: 3.9268x; 1.1077x over previous
#include <cuda_runtime.h>
#include <cstdint>

// ---------------- problem constants ----------------
#define Bz   8
#define Dd   4096
#define TD   512
#define WD   512
#define SLOPE 0.01f

// ---------------- scratch (static device globals) ----------------
__device__ float g_hs [Bz * 65 * Dd];
__device__ float g_q  [Bz * 65 * Dd];
__device__ float g_k  [Bz * 65 * Dd];
__device__ float g_v  [Bz * 65 * Dd];
__device__ float g_sc [Bz * 65 * 65];   // scores / weights (always 65x65 stride)
__device__ float g_a  [Bz * 64 * Dd];
__device__ float g_h  [Bz * 64 * Dd];

// ================= tf32 mma.sync GEMM =================
// C[z][M,4096] = A[M,K] @ W[z][K,4096] + bias[z] (+leaky)
// CTA 128x128, BK=32, 512 thr, warp grid 4x4, warp tile 32x32.
// Staging: LDG -> cvt tf32 -> STS (smem holds tf32 bits); 2 smem stages.

#define ASTRIDE 36
#define BSTRIDE 136
#define A_FLOATS (128 * ASTRIDE)          // 4608
#define B_FLOATS (32 * BSTRIDE)           // 4352
#define STAGE_FLOATS (A_FLOATS + B_FLOATS)
#define GEMM_SMEM (2 * STAGE_FLOATS * 4)  // 71680 bytes

__device__ __forceinline__ uint32_t f2tf32(float x) {
    uint32_t u;
    asm("cvt.rna.tf32.f32 %0, %1;" : "=r"(u) : "f"(x));
    return u;
}

__global__ __launch_bounds__(512, 1)
void mma_gemm(const float* __restrict__ A,
              const float* __restrict__ W0, const float* __restrict__ W1,
              const float* __restrict__ W2,
              const float* __restrict__ b0, const float* __restrict__ b1,
              const float* __restrict__ b2,
              float* __restrict__ C0, float* __restrict__ C1, float* __restrict__ C2,
              int M, int K, int act)
{
    const float* W    = (blockIdx.z == 0) ? W0 : (blockIdx.z == 1) ? W1 : W2;
    const float* bias = (blockIdx.z == 0) ? b0 : (blockIdx.z == 1) ? b1 : b2;
    float*       C    = (blockIdx.z == 0) ? C0 : (blockIdx.z == 1) ? C1 : C2;

    extern __shared__ __align__(16) uint32_t smu[];
    const int tid  = threadIdx.x;
    const int wid  = tid >> 5;
    const int lane = tid & 31;
    const int bn = blockIdx.x << 7;
    const int bm = blockIdx.y << 7;
    const int wm = (wid >> 2) << 5;
    const int wn = (wid & 3) << 5;
    const int r  = lane >> 2;
    const int c  = lane & 3;

    // per-thread staging indices (2 A chunks + 2 B chunks)
    const int a_row0 = tid >> 3,          a_f4 = tid & 7;        // +64 rows for chunk 1
    const int b_row0 = tid >> 5,          b_f4 = tid & 31;       // +16 rows for chunk 1

    float acc[2][4][4];
    #pragma unroll
    for (int i = 0; i < 2; i++)
        #pragma unroll
        for (int j = 0; j < 4; j++)
            #pragma unroll
            for (int t = 0; t < 4; t++) acc[i][j][t] = 0.f;

    const int nkb = K >> 5;
    float4 ar[2], br[2];

    auto ldg_stage = [&](int kb) {
        const int kcol = kb << 5;
        #pragma unroll
        for (int i = 0; i < 2; i++) {
            int row = a_row0 + i * 64;
            int gm  = bm + row;
            ar[i] = (gm < M) ? *(const float4*)(A + (size_t)gm * K + kcol + a_f4 * 4)
                             : make_float4(0.f, 0.f, 0.f, 0.f);
        }
        #pragma unroll
        for (int i = 0; i < 2; i++) {
            int row = b_row0 + i * 16;
            br[i] = *(const float4*)(W + (size_t)(kcol + row) * 4096 + bn + b_f4 * 4);
        }
    };

    auto sts_stage = [&](int buf) {
        uint32_t* as_ = smu + buf * STAGE_FLOATS;
        uint32_t* bs_ = as_ + A_FLOATS;
        #pragma unroll
        for (int i = 0; i < 2; i++) {
            int row = a_row0 + i * 64;
            uint4 u = make_uint4(f2tf32(ar[i].x), f2tf32(ar[i].y),
                                 f2tf32(ar[i].z), f2tf32(ar[i].w));
            *(uint4*)(as_ + row * ASTRIDE + a_f4 * 4) = u;
        }
        #pragma unroll
        for (int i = 0; i < 2; i++) {
            int row = b_row0 + i * 16;
            uint4 u = make_uint4(f2tf32(br[i].x), f2tf32(br[i].y),
                                 f2tf32(br[i].z), f2tf32(br[i].w));
            *(uint4*)(bs_ + row * BSTRIDE + b_f4 * 4) = u;
        }
    };

    ldg_stage(0);

    for (int kb = 0; kb < nkb; kb++) {
        sts_stage(kb & 1);
        __syncthreads();
        if (kb + 1 < nkb) ldg_stage(kb + 1);

        const uint32_t* as = smu + (kb & 1) * STAGE_FLOATS;
        const uint32_t* bs = as + A_FLOATS;

        #pragma unroll
        for (int ks = 0; ks < 4; ks++) {
            const int k0 = ks << 3;
            uint32_t af[2][4];
            #pragma unroll
            for (int mt = 0; mt < 2; mt++) {
                int m = wm + mt * 16 + r;
                af[mt][0] = as[ m      * ASTRIDE + k0 + c    ];
                af[mt][1] = as[(m + 8) * ASTRIDE + k0 + c    ];
                af[mt][2] = as[ m      * ASTRIDE + k0 + c + 4];
                af[mt][3] = as[(m + 8) * ASTRIDE + k0 + c + 4];
            }
            uint32_t bf[4][2];
            #pragma unroll
            for (int nt = 0; nt < 4; nt++) {
                int n = wn + nt * 8 + r;
                bf[nt][0] = bs[(k0 + c)     * BSTRIDE + n];
                bf[nt][1] = bs[(k0 + 4 + c) * BSTRIDE + n];
            }
            #pragma unroll
            for (int mt = 0; mt < 2; mt++)
                #pragma unroll
                for (int nt = 0; nt < 4; nt++) {
                    asm volatile(
                        "mma.sync.aligned.m16n8k8.row.col.f32.tf32.tf32.f32 "
                        "{%0,%1,%2,%3}, {%4,%5,%6,%7}, {%8,%9}, {%0,%1,%2,%3};"
                        : "+f"(acc[mt][nt][0]), "+f"(acc[mt][nt][1]),
                          "+f"(acc[mt][nt][2]), "+f"(acc[mt][nt][3])
                        : "r"(af[mt][0]), "r"(af[mt][1]), "r"(af[mt][2]), "r"(af[mt][3]),
                          "r"(bf[nt][0]), "r"(bf[nt][1]));
                }
        }
        __syncthreads();
    }

    #pragma unroll
    for (int mt = 0; mt < 2; mt++) {
        int row0 = bm + wm + mt * 16 + r;
        int row1 = row0 + 8;
        #pragma unroll
        for (int nt = 0; nt < 4; nt++) {
            int col = bn + wn + nt * 8 + c * 2;
            float bb0 = bias[col], bb1 = bias[col + 1];
            if (row0 < M) {
                float v0 = acc[mt][nt][0] + bb0;
                float v1 = acc[mt][nt][1] + bb1;
                if (act) { v0 = v0 >= 0.f ? v0 : SLOPE * v0; v1 = v1 >= 0.f ? v1 : SLOPE * v1; }
                *(float2*)(C + (size_t)row0 * 4096 + col) = make_float2(v0, v1);
            }
            if (row1 < M) {
                float v2 = acc[mt][nt][2] + bb0;
                float v3 = acc[mt][nt][3] + bb1;
                if (act) { v2 = v2 >= 0.f ? v2 : SLOPE * v2; v3 = v3 >= 0.f ? v3 : SLOPE * v3; }
                *(float2*)(C + (size_t)row1 * 4096 + col) = make_float2(v2, v3);
            }
        }
    }
}

// ================= attention =================

__global__ void zero_sc_kernel(float* sc)
{
    int idx = blockIdx.x * blockDim.x + threadIdx.x;
    if (idx < Bz * 65 * 65) sc[idx] = 0.f;
}

// partial scores: for d-chunk ch, add 2*<q_i,k_j>_ch - |k_j|^2_ch into SC[b][i][j]
// smem: Qs/Ks transposed [kk][idx], row stride 81 (conflict-free).
#define SCW 81
#define SC_SMEM (2 * 128 * SCW * 4)   // 82944 bytes

__global__ __launch_bounds__(256)
void attn_scores_part(const float* __restrict__ Q, const float* __restrict__ Km,
                      float* __restrict__ SC, int Sq, int Sk, int qbs, int kbs)
{
    extern __shared__ __align__(16) float sq[];
    float* sk = sq + 128 * SCW;
    __shared__ float kn[80];

    const int b  = blockIdx.y;
    const int ch = blockIdx.x;            // 0..31
    const int tid = threadIdx.x;
    const int ty = tid >> 4, tx = tid & 15;

    // stage Q chunk transposed
    for (int e = tid; e < Sq * 128; e += 256) {
        int i  = e >> 7;
        int kk = e & 127;
        sq[kk * SCW + i] = Q[((size_t)b * qbs + i) * Dd + ch * 128 + kk];
    }
    for (int e = tid; e < Sk * 128; e += 256) {
        int j  = e >> 7;
        int kk = e & 127;
        sk[kk * SCW + j] = Km[((size_t)b * kbs + j) * Dd + ch * 128 + kk];
    }
    __syncthreads();

    // per-chunk key norms
    if (tid < Sk) {
        float s = 0.f;
        #pragma unroll 8
        for (int kk = 0; kk < 128; kk++) {
            float v = sk[kk * SCW + tid];
            s += v * v;
        }
        kn[tid] = s;
    }
    __syncthreads();

    float acc[5][5];
    #pragma unroll
    for (int u = 0; u < 5; u++)
        #pragma unroll
        for (int v = 0; v < 5; v++) acc[u][v] = 0.f;

    #pragma unroll 4
    for (int kk = 0; kk < 128; kk++) {
        float a[5], bb[5];
        #pragma unroll
        for (int u = 0; u < 5; u++) a[u]  = sq[kk * SCW + ty * 5 + u];
        #pragma unroll
        for (int v = 0; v < 5; v++) bb[v] = sk[kk * SCW + tx * 5 + v];
        #pragma unroll
        for (int u = 0; u < 5; u++)
            #pragma unroll
            for (int v = 0; v < 5; v++) acc[u][v] += a[u] * bb[v];
    }

    #pragma unroll
    for (int u = 0; u < 5; u++) {
        int i = ty * 5 + u;
        if (i >= Sq) continue;
        #pragma unroll
        for (int v = 0; v < 5; v++) {
            int j = tx * 5 + v;
            if (j >= Sk) continue;
            atomicAdd(&SC[((size_t)b * 65 + i) * 65 + j], 2.f * acc[u][v] - kn[j]);
        }
    }
}

// in-place softmax over keys: one warp per (b, i) row
__global__ __launch_bounds__(32)
void softmax_kernel(float* __restrict__ SC, int Sk)
{
    int b = blockIdx.y, i = blockIdx.x;
    float* row = SC + ((size_t)b * 65 + i) * 65;
    int lane = threadIdx.x;

    float v0 = (lane      < Sk) ? row[lane]      : -1e30f;
    float v1 = (lane + 32 < Sk) ? row[lane + 32] : -1e30f;
    float v2 = (lane + 64 < Sk) ? row[lane + 64] : -1e30f;
    float mx = fmaxf(v0, fmaxf(v1, v2));
    #pragma unroll
    for (int o = 16; o; o >>= 1) mx = fmaxf(mx, __shfl_xor_sync(0xffffffff, mx, o));
    float e0 = (lane      < Sk) ? __expf(v0 - mx) : 0.f;
    float e1 = (lane + 32 < Sk) ? __expf(v1 - mx) : 0.f;
    float e2 = (lane + 64 < Sk) ? __expf(v2 - mx) : 0.f;
    float s = e0 + e1 + e2;
    #pragma unroll
    for (int o = 16; o; o >>= 1) s += __shfl_xor_sync(0xffffffff, s, o);
    float inv = 1.f / s;
    if (lane      < Sk) row[lane]      = e0 * inv;
    if (lane + 32 < Sk) row[lane + 32] = e1 * inv;
    if (lane + 64 < Sk) row[lane + 64] = e2 * inv;
}

// attention out, d-chunked: Out[b][j][ch] = sum_i w[i][j] * V[b][i][ch]
// 256 threads: tx=0..31 (4 d-cols each), ty=0..7 (8 j each). Out j range = 64.
#define AO_SMEM ((65 * 128 + 65 * 64) * 4)  // 49920 bytes

__global__ __launch_bounds__(256)
void attn_out_chunk(const float* __restrict__ SC, const float* __restrict__ V,
                    float* __restrict__ Out, int Sq, int vbs)
{
    extern __shared__ __align__(16) float svs[];
    float* sw = svs + 65 * 128;

    const int b  = blockIdx.y;
    const int ch = blockIdx.x;
    const int tid = threadIdx.x;
    const int tx = tid & 31, ty = tid >> 5;

    for (int e = tid; e < Sq * 128; e += 256) {
        int i  = e >> 7;
        int kk = e & 127;
        svs[e] = V[((size_t)b * vbs + i) * Dd + ch * 128 + kk];
    }
    for (int e = tid; e < Sq * 64; e += 256) {
        int i = e >> 6;
        int j = e & 63;
        sw[e] = SC[((size_t)b * 65 + i) * 65 + j];
    }
    __syncthreads();

    float acc[8][4];
    #pragma unroll
    for (int u = 0; u < 8; u++)
        #pragma unroll
        for (int t = 0; t < 4; t++) acc[u][t] = 0.f;

    for (int i = 0; i < Sq; i++) {
        float4 v4 = *(const float4*)(svs + i * 128 + tx * 4);
        #pragma unroll
        for (int u = 0; u < 8; u++) {
            float w = sw[i * 64 + ty * 8 + u];
            acc[u][0] += w * v4.x;
            acc[u][1] += w * v4.y;
            acc[u][2] += w * v4.z;
            acc[u][3] += w * v4.w;
        }
    }

    #pragma unroll
    for (int u = 0; u < 8; u++) {
        int j = ty * 8 + u;
        *(float4*)(Out + ((size_t)b * 64 + j) * Dd + ch * 128 + tx * 4) =
            make_float4(acc[u][0], acc[u][1], acc[u][2], acc[u][3]);
    }
}

// ================= layout kernels =================
__global__ void patchify_kernel(const float* __restrict__ x, float* __restrict__ hs)
{
    int idx = blockIdx.x * blockDim.x + threadIdx.x;
    if (idx >= Bz * 64 * Dd) return;
    int d  = idx & 4095;
    int n  = (idx >> 12) & 63;
    int b  = idx >> 18;
    int cc = d & 63;
    int pp = d >> 6;
    int pr = pp >> 3, pc = pp & 7;
    int ib = n >> 3, jb = n & 7;
    int y  = jb * 8 + pr;
    int xw = ib * 8 + pc;
    hs[((size_t)b * 65 + n) * Dd + d] =
        x[(((size_t)b * 64 + cc) * 64 + y) * 64 + xw];
}

__global__ void style_kernel(const float* __restrict__ w, const float* __restrict__ sw,
                             const float* __restrict__ sb, float* __restrict__ hs)
{
    int o = blockIdx.x * blockDim.x + threadIdx.x;
    int b = blockIdx.y;
    const float* wb = w + (size_t)b * WD;
    float acc = sb[o];
    #pragma unroll 4
    for (int k = 0; k < WD; k++)
        acc += wb[k] * sw[(size_t)k * Dd + o];
    hs[((size_t)b * 65 + 64) * Dd + o] = acc;
}

__global__ void depatchify_kernel(const float* __restrict__ h, float* __restrict__ out)
{
    int idx = blockIdx.x * blockDim.x + threadIdx.x;
    if (idx >= Bz * 64 * 64 * 64) return;
    int xw = idx & 63;
    int y  = (idx >> 6) & 63;
    int cc = (idx >> 12) & 63;
    int b  = idx >> 18;
    int jb = y >> 3, pr = y & 7;
    int ib = xw >> 3, pc = xw & 7;
    int n = ib * 8 + jb;
    int d = (pr * 8 + pc) * 64 + cc;
    out[idx] = h[((size_t)b * 64 + n) * Dd + d];
}

// ================= host sequence =================
static void run_gemm3(const float* A,
                      const float* W0, const float* W1, const float* W2,
                      const float* b0, const float* b1, const float* b2,
                      float* C0, float* C1, float* C2,
                      int M, int K, int nz, int act)
{
    dim3 grid(32, (M + 127) / 128, nz);
    mma_gemm<<<grid, 512, GEMM_SMEM>>>(A, W0, W1, W2, b0, b1, b2,
                                       C0, C1, C2, M, K, act);
}

static void run_attention(const float* q, const float* k, const float* v,
                          float* sc, float* a, int Sq, int Sk,
                          int qbs, int kbs, int vbs)
{
    zero_sc_kernel<<<(Bz * 65 * 65 + 255) / 256, 256>>>(sc);
    attn_scores_part<<<dim3(32, Bz), 256, SC_SMEM>>>(q, k, sc, Sq, Sk, qbs, kbs);
    softmax_kernel<<<dim3(Sq, Bz), 32>>>(sc, Sk);
    attn_out_chunk<<<dim3(32, Bz), 256, AO_SMEM>>>(sc, v, a, Sq, vbs);
}

extern "C" void kernel_launch(void* const* d_in, const int* in_sizes, int n_in,
                              void* d_out, int out_size)
{
    const float* x          = (const float*)d_in[0];
    const float* w          = (const float*)d_in[1];
    const float* t_local    = (const float*)d_in[2];
    const float* sa_style_w = (const float*)d_in[3];
    const float* sa_style_b = (const float*)d_in[4];
    const float* sa_kk = (const float*)d_in[5];
    const float* sa_kb = (const float*)d_in[6];
    const float* sa_qk = (const float*)d_in[7];
    const float* sa_qb = (const float*)d_in[8];
    const float* sa_vk = (const float*)d_in[9];
    const float* sa_vb = (const float*)d_in[10];
    const float* sa_ok = (const float*)d_in[11];
    const float* sa_ob = (const float*)d_in[12];
    const float* ca_kk = (const float*)d_in[13];
    const float* ca_kb = (const float*)d_in[14];
    const float* ca_qk = (const float*)d_in[15];
    const float* ca_qb = (const float*)d_in[16];
    const float* ca_vk = (const float*)d_in[17];
    const float* ca_vb = (const float*)d_in[18];
    const float* ca_ok = (const float*)d_in[19];
    const float* ca_ob = (const float*)d_in[20];
    float* out = (float*)d_out;

    float *hs, *q, *k, *v, *sc, *a, *h;
    cudaGetSymbolAddress((void**)&hs, g_hs);
    cudaGetSymbolAddress((void**)&q,  g_q);
    cudaGetSymbolAddress((void**)&k,  g_k);
    cudaGetSymbolAddress((void**)&v,  g_v);
    cudaGetSymbolAddress((void**)&sc, g_sc);
    cudaGetSymbolAddress((void**)&a,  g_a);
    cudaGetSymbolAddress((void**)&h,  g_h);

    cudaFuncSetAttribute(mma_gemm, cudaFuncAttributeMaxDynamicSharedMemorySize, GEMM_SMEM);
    cudaFuncSetAttribute(attn_scores_part, cudaFuncAttributeMaxDynamicSharedMemorySize, SC_SMEM);
    cudaFuncSetAttribute(attn_out_chunk, cudaFuncAttributeMaxDynamicSharedMemorySize, AO_SMEM);

    // 1. patchify + style token -> hs (B,65,D)
    patchify_kernel<<<(Bz * 64 * Dd + 255) / 256, 256>>>(x, hs);
    style_kernel<<<dim3(Dd / 256, Bz), 256>>>(w, sa_style_w, sa_style_b, hs);

    // 2. SA q/k/v projections, fused (M=520, K=4096, z=3)
    run_gemm3(hs, sa_qk, sa_kk, sa_vk, sa_qb, sa_kb, sa_vb,
              q, k, v, Bz * 65, Dd, 3, 0);

    // 3. SA L2 attention (Sq=Sk=65, out keys 0..63)
    run_attention(q, k, v, sc, a, 65, 65, 65, 65, 65);

    // 4. SA output projection + leaky relu
    run_gemm3(a, sa_ok, sa_ok, sa_ok, sa_ob, sa_ob, sa_ob,
              h, h, h, Bz * 64, Dd, 1, 1);

    // 5. CA projections: k from h; q/v from t_local fused (z=2)
    run_gemm3(h, ca_kk, ca_kk, ca_kk, ca_kb, ca_kb, ca_kb,
              k, k, k, Bz * 64, Dd, 1, 0);
    run_gemm3(t_local, ca_qk, ca_vk, ca_vk, ca_qb, ca_vb, ca_vb,
              q, v, v, Bz * 64, TD, 2, 0);

    // 6. CA L2 attention (Sq=64, Sk=64)
    run_attention(q, k, v, sc, a, 64, 64, 64, 64, 64);

    // 7. CA output projection + leaky relu
    run_gemm3(a, ca_ok, ca_ok, ca_ok, ca_ob, ca_ob, ca_ob,
              h, h, h, Bz * 64, Dd, 1, 1);

    // 8. depatchify
    depatchify_kernel<<<(Bz * 64 * 64 * 64 + 255) / 256, 256>>>(h, out);
}